// round 2
// baseline (speedup 1.0000x reference)
#include <cuda_runtime.h>
#include <cstdint>

// FlashAttention: B=2, S=2048, H=16, D=64, fp32 in/out, key_padding_mask int32 (nonzero => -inf).
// Split-tf32 (3xTF32) flash-attention-2 kernel: fp32-grade accuracy on HMMA tf32 pipe.

#define B_DIM 2
#define S_DIM 2048
#define H_DIM 16
#define D_DIM 64
#define BM 128           // query rows per CTA
#define BN 64            // key cols per iteration
#define THREADS 256
#define LDK 68           // K smem stride (68 mod 32 == 4 -> conflict-free for K B-frag pattern)
#define LDV 72           // V smem stride (72 mod 32 == 8 -> conflict-free for V B-frag pattern)

__device__ __forceinline__ uint32_t f2tf32(float f) {
    uint32_t r;
    asm("cvt.rna.tf32.f32 %0, %1;" : "=r"(r) : "f"(f));
    return r;
}
__device__ __forceinline__ void split_tf32(float a, uint32_t& hi, uint32_t& lo) {
    hi = f2tf32(a);
    lo = f2tf32(a - __uint_as_float(hi));
}
__device__ __forceinline__ float ex2(float x) {
    float r;
    asm("ex2.approx.f32 %0, %1;" : "=f"(r) : "f"(x));
    return r;
}
__device__ __forceinline__ void mma_tf32(float c[4],
                                         uint32_t a0, uint32_t a1, uint32_t a2, uint32_t a3,
                                         uint32_t b0, uint32_t b1) {
    asm volatile("mma.sync.aligned.m16n8k8.row.col.f32.tf32.tf32.f32 "
                 "{%0,%1,%2,%3}, {%4,%5,%6,%7}, {%8,%9}, {%0,%1,%2,%3};"
                 : "+f"(c[0]), "+f"(c[1]), "+f"(c[2]), "+f"(c[3])
                 : "r"(a0), "r"(a1), "r"(a2), "r"(a3), "r"(b0), "r"(b1));
}

// smem (floats): sKh [BN*LDK] | sKl [BN*LDK] | sVh [BN*LDV] | sVl [BN*LDV] | mb [BN]
#define SMEM_FLOATS (2 * BN * LDK + 2 * BN * LDV + BN)

__global__ void __launch_bounds__(THREADS, 1)
fa_3xtf32_kernel(const float* __restrict__ q, const float* __restrict__ k,
                 const float* __restrict__ v, const int* __restrict__ mask,
                 float* __restrict__ out) {
    extern __shared__ float smem[];
    uint32_t* sKh = reinterpret_cast<uint32_t*>(smem);
    uint32_t* sKl = sKh + BN * LDK;
    uint32_t* sVh = sKl + BN * LDK;
    uint32_t* sVl = sVh + BN * LDV;
    float*    mb  = reinterpret_cast<float*>(sVl + BN * LDV);

    const int tid  = threadIdx.x;
    const int w    = tid >> 5;
    const int lane = tid & 31;
    const int g    = lane >> 2;       // row group 0..7
    const int j    = lane & 3;        // col group 0..3
    const int bh   = blockIdx.y;      // b*H + h
    const int b    = bh >> 4;         // H = 16
    const int h    = bh & 15;
    const int m0   = blockIdx.x * BM;

    const int base = b * (S_DIM * H_DIM * D_DIM) + h * D_DIM;   // (s,d): base + s*1024 + d
    const int rs   = H_DIM * D_DIM;                             // 1024

    const float sc = 0.125f * 1.44269504088896f;  // D^-0.5 * log2(e), folded into Q

    // ---- Q fragments (hi/lo split), loaded once from gmem ----
    const int r0 = w * 16 + g;
    uint32_t rQh[8][4], rQl[8][4];
    {
        const float* q0 = q + base + (m0 + r0) * rs;
        const float* q1 = q0 + 8 * rs;
        #pragma unroll
        for (int kc = 0; kc < 8; ++kc) {
            int c = kc * 8 + j;
            split_tf32(q0[c]     * sc, rQh[kc][0], rQl[kc][0]);
            split_tf32(q1[c]     * sc, rQh[kc][1], rQl[kc][1]);
            split_tf32(q0[c + 4] * sc, rQh[kc][2], rQl[kc][2]);
            split_tf32(q1[c + 4] * sc, rQh[kc][3], rQl[kc][3]);
        }
    }

    float rO[8][4];
    #pragma unroll
    for (int i = 0; i < 8; ++i)
        #pragma unroll
        for (int t = 0; t < 4; ++t) rO[i][t] = 0.0f;
    float mrow0 = -1e30f, mrow1 = -1e30f;
    float lrow0 = 0.0f,   lrow1 = 0.0f;

    for (int nb = 0; nb < S_DIM / BN; ++nb) {
        const int n0 = nb * BN;

        // ---- stage K/V tile -> smem with hi/lo split ----
        #pragma unroll
        for (int i = 0; i < (BN * D_DIM / 4) / THREADS; ++i) {  // 4 iters
            int e  = i * THREADS + tid;
            int r  = e >> 4;
            int c4 = (e & 15) << 2;
            int gidx = base + (n0 + r) * rs + c4;
            float4 kv = *reinterpret_cast<const float4*>(k + gidx);
            float4 vv = *reinterpret_cast<const float4*>(v + gidx);
            uint32_t h0,h1,h2,h3,l0,l1,l2,l3;
            split_tf32(kv.x,h0,l0); split_tf32(kv.y,h1,l1);
            split_tf32(kv.z,h2,l2); split_tf32(kv.w,h3,l3);
            *reinterpret_cast<uint4*>(sKh + r * LDK + c4) = make_uint4(h0,h1,h2,h3);
            *reinterpret_cast<uint4*>(sKl + r * LDK + c4) = make_uint4(l0,l1,l2,l3);
            split_tf32(vv.x,h0,l0); split_tf32(vv.y,h1,l1);
            split_tf32(vv.z,h2,l2); split_tf32(vv.w,h3,l3);
            *reinterpret_cast<uint4*>(sVh + r * LDV + c4) = make_uint4(h0,h1,h2,h3);
            *reinterpret_cast<uint4*>(sVl + r * LDV + c4) = make_uint4(l0,l1,l2,l3);
        }
        if (tid < BN) mb[tid] = mask[b * S_DIM + n0 + tid] ? -1e30f : 0.0f;
        __syncthreads();

        // ---- S = (Q*sc) @ K^T  (3xTF32) ----
        float rS[8][4];
        #pragma unroll
        for (int i = 0; i < 8; ++i)
            #pragma unroll
            for (int t = 0; t < 4; ++t) rS[i][t] = 0.0f;

        #pragma unroll
        for (int kc = 0; kc < 8; ++kc) {
            uint32_t bh_[8][2], bl_[8][2];
            #pragma unroll
            for (int nc = 0; nc < 8; ++nc) {
                int rb = (nc * 8 + g) * LDK + kc * 8 + j;
                bh_[nc][0] = sKh[rb]; bh_[nc][1] = sKh[rb + 4];
                bl_[nc][0] = sKl[rb]; bl_[nc][1] = sKl[rb + 4];
            }
            #pragma unroll
            for (int nc = 0; nc < 8; ++nc)
                mma_tf32(rS[nc], rQh[kc][0], rQh[kc][1], rQh[kc][2], rQh[kc][3],
                         bh_[nc][0], bh_[nc][1]);
            #pragma unroll
            for (int nc = 0; nc < 8; ++nc)
                mma_tf32(rS[nc], rQh[kc][0], rQh[kc][1], rQh[kc][2], rQh[kc][3],
                         bl_[nc][0], bl_[nc][1]);
            #pragma unroll
            for (int nc = 0; nc < 8; ++nc)
                mma_tf32(rS[nc], rQl[kc][0], rQl[kc][1], rQl[kc][2], rQl[kc][3],
                         bh_[nc][0], bh_[nc][1]);
        }

        // ---- mask + online softmax (log2 domain) ----
        float mx0 = -1e30f, mx1 = -1e30f;
        #pragma unroll
        for (int nc = 0; nc < 8; ++nc) {
            int c = nc * 8 + 2 * j;
            float b0 = mb[c], b1 = mb[c + 1];
            rS[nc][0] += b0; rS[nc][1] += b1;
            rS[nc][2] += b0; rS[nc][3] += b1;
            mx0 = fmaxf(mx0, fmaxf(rS[nc][0], rS[nc][1]));
            mx1 = fmaxf(mx1, fmaxf(rS[nc][2], rS[nc][3]));
        }
        mx0 = fmaxf(mx0, __shfl_xor_sync(0xffffffffu, mx0, 1));
        mx0 = fmaxf(mx0, __shfl_xor_sync(0xffffffffu, mx0, 2));
        mx1 = fmaxf(mx1, __shfl_xor_sync(0xffffffffu, mx1, 1));
        mx1 = fmaxf(mx1, __shfl_xor_sync(0xffffffffu, mx1, 2));

        float mn0 = fmaxf(mrow0, mx0);
        float mn1 = fmaxf(mrow1, mx1);
        float al0 = ex2(mrow0 - mn0);
        float al1 = ex2(mrow1 - mn1);
        mrow0 = mn0; mrow1 = mn1;

        float sum0 = 0.0f, sum1 = 0.0f;
        #pragma unroll
        for (int nc = 0; nc < 8; ++nc) {
            rS[nc][0] = ex2(rS[nc][0] - mn0);
            rS[nc][1] = ex2(rS[nc][1] - mn0);
            rS[nc][2] = ex2(rS[nc][2] - mn1);
            rS[nc][3] = ex2(rS[nc][3] - mn1);
            sum0 += rS[nc][0] + rS[nc][1];
            sum1 += rS[nc][2] + rS[nc][3];
        }
        sum0 += __shfl_xor_sync(0xffffffffu, sum0, 1);
        sum0 += __shfl_xor_sync(0xffffffffu, sum0, 2);
        sum1 += __shfl_xor_sync(0xffffffffu, sum1, 1);
        sum1 += __shfl_xor_sync(0xffffffffu, sum1, 2);
        lrow0 = lrow0 * al0 + sum0;
        lrow1 = lrow1 * al1 + sum1;

        #pragma unroll
        for (int nc = 0; nc < 8; ++nc) {
            rO[nc][0] *= al0; rO[nc][1] *= al0;
            rO[nc][2] *= al1; rO[nc][3] *= al1;
        }

        // ---- PV: relayout P via shfl (C-frag -> A-frag), split, 3xTF32 mma ----
        const int srcA = (lane & 28) | (j >> 1);
        const int srcB = srcA + 2;
        #pragma unroll
        for (int kc = 0; kc < 8; ++kc) {
            float v0a = __shfl_sync(0xffffffffu, rS[kc][0], srcA);
            float v1a = __shfl_sync(0xffffffffu, rS[kc][1], srcA);
            float v2a = __shfl_sync(0xffffffffu, rS[kc][2], srcA);
            float v3a = __shfl_sync(0xffffffffu, rS[kc][3], srcA);
            float v0b = __shfl_sync(0xffffffffu, rS[kc][0], srcB);
            float v1b = __shfl_sync(0xffffffffu, rS[kc][1], srcB);
            float v2b = __shfl_sync(0xffffffffu, rS[kc][2], srcB);
            float v3b = __shfl_sync(0xffffffffu, rS[kc][3], srcB);
            bool odd = (j & 1);
            float pa0 = odd ? v1a : v0a;   // P[r0   ][kc*8 + j    ]
            float pa1 = odd ? v3a : v2a;   // P[r0+8 ][kc*8 + j    ]
            float pa2 = odd ? v1b : v0b;   // P[r0   ][kc*8 + j + 4]
            float pa3 = odd ? v3b : v2b;   // P[r0+8 ][kc*8 + j + 4]
            uint32_t ph0,ph1,ph2,ph3, pl0,pl1,pl2,pl3;
            split_tf32(pa0, ph0, pl0); split_tf32(pa1, ph1, pl1);
            split_tf32(pa2, ph2, pl2); split_tf32(pa3, ph3, pl3);

            uint32_t vh_[8][2], vl_[8][2];
            #pragma unroll
            for (int nc = 0; nc < 8; ++nc) {
                int rb = (kc * 8 + j) * LDV + nc * 8 + g;
                vh_[nc][0] = sVh[rb]; vh_[nc][1] = sVh[rb + 4 * LDV];
                vl_[nc][0] = sVl[rb]; vl_[nc][1] = sVl[rb + 4 * LDV];
            }
            #pragma unroll
            for (int nc = 0; nc < 8; ++nc)
                mma_tf32(rO[nc], ph0, ph1, ph2, ph3, vh_[nc][0], vh_[nc][1]);
            #pragma unroll
            for (int nc = 0; nc < 8; ++nc)
                mma_tf32(rO[nc], ph0, ph1, ph2, ph3, vl_[nc][0], vl_[nc][1]);
            #pragma unroll
            for (int nc = 0; nc < 8; ++nc)
                mma_tf32(rO[nc], pl0, pl1, pl2, pl3, vh_[nc][0], vh_[nc][1]);
        }
        __syncthreads();  // protect sK/sV/mb before next stage
    }

    // ---- epilogue: normalize and store ----
    float inv0 = 1.0f / lrow0;
    float inv1 = 1.0f / lrow1;
    #pragma unroll
    for (int nc = 0; nc < 8; ++nc) {
        int c = nc * 8 + 2 * j;
        float2 o0 = make_float2(rO[nc][0] * inv0, rO[nc][1] * inv0);
        float2 o1 = make_float2(rO[nc][2] * inv1, rO[nc][3] * inv1);
        *reinterpret_cast<float2*>(out + base + (m0 + r0) * rs + c) = o0;
        *reinterpret_cast<float2*>(out + base + (m0 + r0 + 8) * rs + c) = o1;
    }
}

extern "C" void kernel_launch(void* const* d_in, const int* in_sizes, int n_in,
                              void* d_out, int out_size) {
    const float* q = (const float*)d_in[0];
    const float* k = (const float*)d_in[1];
    const float* v = (const float*)d_in[2];
    const int*   mask = (const int*)d_in[3];
    float* out = (float*)d_out;

    static_assert(SMEM_FLOATS * sizeof(float) < 100 * 1024, "smem budget");
    cudaFuncSetAttribute(fa_3xtf32_kernel, cudaFuncAttributeMaxDynamicSharedMemorySize,
                         SMEM_FLOATS * sizeof(float));

    dim3 grid(S_DIM / BM, B_DIM * H_DIM);
    dim3 block(THREADS);
    fa_3xtf32_kernel<<<grid, block, SMEM_FLOATS * sizeof(float)>>>(q, k, v, mask, out);
}